// round 17
// baseline (speedup 1.0000x reference)
#include <cuda_runtime.h>
#include <cuda_fp16.h>

#define BB 128
#define TT 512
#define CC 128

#define EBIAS 2.5f            // E' = exp(trans - EBIAS)
#define KSCALE 0.0212797f     // exp(-GROW), GROW = 3.85
#define MSTEP 6.35f           // EBIAS + GROW added to m each step

__device__ float g_partial[BB];

__device__ __forceinline__ float block_reduce_sum_512(float v, float* sh16) {
    #pragma unroll
    for (int o = 16; o > 0; o >>= 1)
        v += __shfl_xor_sync(0xffffffffu, v, o);
    int w = threadIdx.x >> 5;
    if ((threadIdx.x & 31) == 0) sh16[w] = v;
    __syncthreads();
    float r = 0.f;
    #pragma unroll
    for (int k = 0; k < 16; k++) r += sh16[k];
    __syncthreads();
    return r;
}

// One forward step. ECOL is a register-array NAME (16 half2, register-resident).
// Thread (j, h): quarter-matvec over i in [32h, 32h+32) — 4 uint4 loads = 32
// halves. Combine across quarters via two in-warp packed-fp16 shuffles.
#define CRF_STEP(ECOL, CUR, t)                                                   \
    {                                                                            \
        float c = ((t) == 0) ? 1.0f : __half2float(p_s[CUR][0]);                 \
        float ef_eff = (ef0 * KSCALE) * __fdividef(1.0f, c);                     \
        __half efh = __float2half_rn(ef_eff);                                    \
        float ef2 = ((t) + 2 < L) ? __expf(fb[(size_t)((t) + 2) * CC]) : 1.0f;   \
        const uint4* pv = (const uint4*)(p_s[CUR] + (h << 5));                   \
        __half2 a0 = __floats2half2_rn(0.f, 0.f), a1 = a0, a2 = a0, a3 = a0,     \
                a4 = a0, a5 = a0, a6 = a0, a7 = a0;                              \
        _Pragma("unroll")                                                        \
        for (int ii = 0; ii < 4; ii++) {                                         \
            uint4 q = pv[ii];                                                    \
            __half2 q0 = *reinterpret_cast<__half2*>(&q.x);                      \
            __half2 q1 = *reinterpret_cast<__half2*>(&q.y);                      \
            __half2 q2 = *reinterpret_cast<__half2*>(&q.z);                      \
            __half2 q3 = *reinterpret_cast<__half2*>(&q.w);                      \
            if ((ii & 1) == 0) {                                                 \
                a0 = __hfma2(q0, ECOL[4 * ii + 0], a0);                          \
                a1 = __hfma2(q1, ECOL[4 * ii + 1], a1);                          \
                a2 = __hfma2(q2, ECOL[4 * ii + 2], a2);                          \
                a3 = __hfma2(q3, ECOL[4 * ii + 3], a3);                          \
            } else {                                                             \
                a4 = __hfma2(q0, ECOL[4 * ii + 0], a4);                          \
                a5 = __hfma2(q1, ECOL[4 * ii + 1], a5);                          \
                a6 = __hfma2(q2, ECOL[4 * ii + 2], a6);                          \
                a7 = __hfma2(q3, ECOL[4 * ii + 3], a7);                          \
            }                                                                    \
        }                                                                        \
        __half2 s2 = __hadd2(__hadd2(__hadd2(a0, a1), __hadd2(a2, a3)),          \
                             __hadd2(__hadd2(a4, a5), __hadd2(a6, a7)));         \
        unsigned sv = *reinterpret_cast<unsigned*>(&s2);                         \
        unsigned o1 = __shfl_xor_sync(0xffffffffu, sv, 8);                       \
        s2 = __hadd2(s2, *reinterpret_cast<__half2*>(&o1));                      \
        unsigned sv2 = *reinterpret_cast<unsigned*>(&s2);                        \
        unsigned o2 = __shfl_xor_sync(0xffffffffu, sv2, 16);                     \
        s2 = __hadd2(s2, *reinterpret_cast<__half2*>(&o2));                      \
        __half shh = __hadd(__low2half(s2), __high2half(s2));                    \
        if (h == 0) p_s[(CUR) ^ 1][j] = __hmul(shh, efh);                        \
        m += MSTEP + __logf(c);                                                  \
        ef0 = ef1; ef1 = ef2;                                                    \
        __syncthreads();                                                         \
    }

__global__ __launch_bounds__(512, 1)
void crf_forward_kernel(const float* __restrict__ feats,
                        const int*   __restrict__ mask,
                        const int*   __restrict__ tags,
                        const float* __restrict__ trans)
{
    const int b   = blockIdx.x;
    const int tid = threadIdx.x;
    const int w   = tid >> 5;              // warp 0..15
    const int l   = tid & 31;
    const int j   = (w << 3) | (l & 7);    // class column owned
    const int h   = l >> 3;                // i-quarter 0..3

    __shared__ __align__(16) __half p_s[2][CC];
    __shared__ float sh16[16];

    // ---- sequence length (contiguous prefix mask) ----
    const int* mrow = mask + b * TT;
    const int L = (int)block_reduce_sum_512((float)mrow[tid], sh16);

    // ---- E quarter-column (32 i-values = 16 half2), two rounded copies ----
    __half2 E2a[16], E2b[16];
    #pragma unroll
    for (int ii = 0; ii < 16; ii++) {
        int i0 = (h << 5) + 2 * ii;
        float lo = __expf(trans[(i0 + 0) * CC + j] - EBIAS);  // exp(-1e5)->0
        float hi = __expf(trans[(i0 + 1) * CC + j] - EBIAS);
        __half hlo = __float2half_rn(lo), hhi = __float2half_rn(hi);
        E2a[ii] = __halves2half2(hlo, hhi);
        __half blo = __float2half_rn(2.0f * lo - __half2float(hlo));
        __half bhi = __float2half_rn(2.0f * hi - __half2float(hhi));
        E2b[ii] = __halves2half2(blo, bhi);
    }

    // ---- init: p = one-hot(START) ----
    if (tid < CC) p_s[0][tid] = __float2half_rn((tid == CC - 2) ? 1.0f : 0.0f);
    __syncthreads();

    const float* fb = feats + (size_t)b * TT * CC + j;
    float m   = 0.0f;
    float ef0 = __expf(fb[0]);                        // L >= 1 always
    float ef1 = (L > 1) ? __expf(fb[CC]) : 1.0f;

    // ---- forward scan: 2 steps per trip, ping-pong unrolled ----
    int t = 0;
    int nPairs = L >> 1;
    for (int p = 0; p < nPairs; p++) {
        CRF_STEP(E2a, 0, t); t++;
        CRF_STEP(E2b, 1, t); t++;
    }
    int cur = 0;
    if (t < L) {                 // odd tail step
        CRF_STEP(E2a, 0, t); t++;
        cur = 1;
    }

    // ---- logZ = m + log( sum_j p[j] * exp(trans[j][STOP]) ) ----
    float contrib = (h == 0)
        ? __half2float(p_s[cur][j]) * __expf(trans[j * CC + (CC - 1)]) : 0.0f;
    float tot = block_reduce_sum_512(contrib, sh16);
    float logZ = m + __logf(tot);

    // ---- gold path score (fp32 exact) ----
    const int* tg = tags + b * TT;
    const float* fbase = feats + (size_t)b * TT * CC;
    float sc = 0.0f;
    for (int tt = tid; tt < L; tt += 512)
        sc += fbase[(size_t)tt * CC + tg[tt]];
    for (int k = tid; k <= L; k += 512) {
        int prev = (k == 0) ? (CC - 2) : tg[k - 1];
        int curt = (k == L) ? (CC - 1) : tg[k];
        sc += trans[prev * CC + curt];
    }
    float tots = block_reduce_sum_512(sc, sh16);

    if (tid == 0) g_partial[b] = logZ - tots;
}

__global__ void crf_finalize_kernel(float* __restrict__ out)
{
    __shared__ float s[BB];
    int tid = threadIdx.x;
    s[tid] = g_partial[tid];
    __syncthreads();
    #pragma unroll
    for (int off = 64; off > 0; off >>= 1) {
        if (tid < off) s[tid] += s[tid + off];
        __syncthreads();
    }
    if (tid == 0) out[0] = s[0] / (float)BB;
}

extern "C" void kernel_launch(void* const* d_in, const int* in_sizes, int n_in,
                              void* d_out, int out_size)
{
    const float* feats = (const float*)d_in[0];
    const int*   mask  = (const int*)  d_in[1];
    const int*   tags  = (const int*)  d_in[2];
    const float* trans = (const float*)d_in[3];
    float* out = (float*)d_out;

    crf_forward_kernel<<<BB, 512>>>(feats, mask, tags, trans);
    crf_finalize_kernel<<<1, BB>>>(out);
}